// round 3
// baseline (speedup 1.0000x reference)
#include <cuda_runtime.h>
#include <math.h>

#define NB 32
#define NC 512
#define HW 4096
#define DC 32
#define NS 16
#define RK 32
#define LL 512

// ---------------- scratch (device globals; no allocation) ----------------
__device__ float g_avg[NB * NC];
__device__ float g_max[NB * NC];
__device__ float g_h[NB * DC * LL];              // h[b][d][l] (post-gelu, k=0 orientation)
__device__ float g_delta[NB * 2 * DC * LL];      // delta[b][k][d][l] (post-softplus)
__device__ float g_Bsc[NB * 2 * NS * LL];        // B[b][k][n][l]
__device__ float g_Csc[NB * 2 * NS * LL];        // C[b][k][n][l]
__device__ float g_part[NB * 2 * 2 * LL];        // partial y sums per (b,k,half)[l_out]
__device__ float g_scale[NB * NC];               // 1 + attn

__device__ __forceinline__ float gelu_exact(float v) {
    return 0.5f * v * (1.0f + erff(v * 0.70710678118654752f));
}

// ---------------- K1: avg/max pool over HW per (b,c) ----------------
__global__ __launch_bounds__(256) void pool_kernel(const float* __restrict__ x) {
    int bc = blockIdx.x;
    const float4* xp = (const float4*)(x + (size_t)bc * HW);
    int t = threadIdx.x;

    float4 v0 = __ldg(xp + t);
    float4 v1 = __ldg(xp + t + 256);
    float4 v2 = __ldg(xp + t + 512);
    float4 v3 = __ldg(xp + t + 768);

    float s = ((v0.x + v0.y) + (v0.z + v0.w)) + ((v1.x + v1.y) + (v1.z + v1.w))
            + ((v2.x + v2.y) + (v2.z + v2.w)) + ((v3.x + v3.y) + (v3.z + v3.w));
    float m = fmaxf(fmaxf(fmaxf(v0.x, v0.y), fmaxf(v0.z, v0.w)),
                    fmaxf(fmaxf(v1.x, v1.y), fmaxf(v1.z, v1.w)));
    m = fmaxf(m, fmaxf(fmaxf(fmaxf(v2.x, v2.y), fmaxf(v2.z, v2.w)),
                       fmaxf(fmaxf(v3.x, v3.y), fmaxf(v3.z, v3.w))));

#pragma unroll
    for (int off = 16; off; off >>= 1) {
        s += __shfl_down_sync(0xffffffffu, s, off);
        m = fmaxf(m, __shfl_down_sync(0xffffffffu, m, off));
    }
    __shared__ float ss[8], sm[8];
    int w = t >> 5;
    if ((t & 31) == 0) { ss[w] = s; sm[w] = m; }
    __syncthreads();
    if (t < 8) {
        s = ss[t]; m = sm[t];
#pragma unroll
        for (int off = 4; off; off >>= 1) {
            s += __shfl_down_sync(0xffu, s, off);
            m = fmaxf(m, __shfl_down_sync(0xffu, m, off));
        }
        if (t == 0) {
            g_avg[bc] = s * (1.0f / (float)HW);
            g_max[bc] = m;
        }
    }
}

// ---------------- K2: channel MLP + projections + softplus ----------------
__global__ __launch_bounds__(256) void proj_kernel(
    const float* __restrict__ xcw,   // (2,64,32)
    const float* __restrict__ dtw,   // (2,32,32)
    const float* __restrict__ dtb,   // (2*32)
    const float* __restrict__ wcin,  // (32,2)
    const float* __restrict__ bng, const float* __restrict__ bnb,
    const float* __restrict__ bnm, const float* __restrict__ bnv)
{
    int g = blockIdx.x * 256 + threadIdx.x;
    int b = g >> 10;
    int k = (g >> 9) & 1;
    int l = g & 511;

    __shared__ float sW[64 * 32];
    __shared__ float sD[32 * 32];
    __shared__ float sc[64], sg[32], sb[32], smn[32], svr[32], sbias[32];

    for (int i = threadIdx.x; i < 64 * 32; i += 256) sW[i] = xcw[k * 2048 + i];
    for (int i = threadIdx.x; i < 32 * 32; i += 256) sD[i] = dtw[k * 1024 + i];
    if (threadIdx.x < 64) sc[threadIdx.x] = wcin[threadIdx.x];
    if (threadIdx.x < 32) {
        int t = threadIdx.x;
        sg[t] = bng[t]; sb[t] = bnb[t]; smn[t] = bnm[t]; svr[t] = bnv[t];
        sbias[t] = dtb[k * 32 + t];
    }
    __syncthreads();

    int ll = k ? (511 - l) : l;                    // flipped h index for k=1
    float av = g_avg[b * 512 + ll];
    float mx = g_max[b * 512 + ll];

    float h[32];
#pragma unroll
    for (int d = 0; d < 32; d++) {
        float pre = av * sc[d * 2] + mx * sc[d * 2 + 1];
        pre = (pre - smn[d]) * rsqrtf(svr[d] + 1e-5f);
        pre = pre * sg[d] + sb[d];
        h[d] = gelu_exact(pre);
    }
    if (k == 0) {
#pragma unroll
        for (int d = 0; d < 32; d++) g_h[(b * 32 + d) * 512 + l] = h[d];
    }

    int base = b * 2 + k;
    float r[32];
#pragma unroll 4
    for (int c = 0; c < 64; c++) {
        float acc = 0.f;
#pragma unroll
        for (int d = 0; d < 32; d++) acc = fmaf(h[d], sW[c * 32 + d], acc);
        if (c < 32)       r[c] = acc;
        else if (c < 48)  g_Bsc[(base * 16 + (c - 32)) * 512 + l] = acc;
        else              g_Csc[(base * 16 + (c - 48)) * 512 + l] = acc;
    }
#pragma unroll 4
    for (int d = 0; d < 32; d++) {
        float acc = sbias[d];
#pragma unroll
        for (int rr = 0; rr < 32; rr++) acc = fmaf(r[rr], sD[d * 32 + rr], acc);
        float sp = (acc > 20.f) ? acc : log1pf(__expf(acc));  // softplus
        g_delta[(base * 32 + d) * 512 + l] = sp;
    }
}

// ---------------- K3: selective scan ----------------
#define SSTR 17   // smem row stride (pad to avoid bank conflicts)
__global__ __launch_bounds__(256) void scan_kernel(
    const float* __restrict__ Ac_logs,  // (64,16)
    const float* __restrict__ Dcs,      // (64)
    const float* __restrict__ wcout)    // (32)
{
    extern __shared__ float smem[];
    float* dsm = smem;                 // [l][dd]  512*SSTR
    float* usm = dsm + 512 * SSTR;
    float* bsm = usm + 512 * SSTR;
    float* csm = bsm + 512 * SSTR;

    int blk = blockIdx.x;
    int b = blk >> 2;
    int k = (blk >> 1) & 1;
    int half = blk & 1;
    int d0 = half * 16;
    int base = b * 2 + k;

    for (int i = threadIdx.x; i < 16 * 512; i += 256) {
        int n = i >> 9, l = i & 511;
        bsm[l * SSTR + n] = g_Bsc[(base * 16 + n) * 512 + l];
        csm[l * SSTR + n] = g_Csc[(base * 16 + n) * 512 + l];
        int d = d0 + n;
        dsm[l * SSTR + n] = g_delta[(base * 32 + d) * 512 + l];
        int lu = k ? (511 - l) : l;
        usm[l * SSTR + n] = g_h[(b * 32 + d) * 512 + lu];
    }
    __syncthreads();

    int warp = threadIdx.x >> 5, lane = threadIdx.x & 31;
    int sub = lane >> 4;        // half-warp id
    int n = lane & 15;          // state index
    int dd = warp * 2 + sub;    // local d (0..15)
    int d = d0 + dd;
    int kd = k * 32 + d;

    float a  = -expf(Ac_logs[kd * 16 + n]);
    float Dv = Dcs[kd];
    float h = 0.f;

#pragma unroll 2
    for (int l = 0; l < 512; l++) {
        float delta = dsm[l * SSTR + dd];
        float u     = usm[l * SSTR + dd];
        float Bn    = bsm[l * SSTR + n];
        float Cn    = csm[l * SSTR + n];
        float dA = __expf(delta * a);
        h = fmaf(dA, h, delta * Bn * u);
        float c = h * Cn;
        c += __shfl_down_sync(0xffffffffu, c, 8, 16);
        c += __shfl_down_sync(0xffffffffu, c, 4, 16);
        c += __shfl_down_sync(0xffffffffu, c, 2, 16);
        c += __shfl_down_sync(0xffffffffu, c, 1, 16);
        if (n == 0) dsm[l * SSTR + dd] = fmaf(Dv, u, c);   // y over consumed delta slot
    }
    __syncthreads();

    for (int l = threadIdx.x; l < 512; l += 256) {
        float acc = 0.f;
#pragma unroll
        for (int dd2 = 0; dd2 < 16; dd2++)
            acc = fmaf(dsm[l * SSTR + dd2], wcout[d0 + dd2], acc);
        int lo = k ? (511 - l) : l;
        g_part[(base * 2 + half) * 512 + lo] = acc;
    }
}

// ---------------- K4: gelu + LayerNorm over L -> 1+attn ----------------
__global__ __launch_bounds__(512) void ln_kernel(
    const float* __restrict__ lng, const float* __restrict__ lnb)
{
    int b = blockIdx.x;
    int l = threadIdx.x;   // 512 threads
    float y = g_part[(b * 4 + 0) * 512 + l] + g_part[(b * 4 + 1) * 512 + l]
            + g_part[(b * 4 + 2) * 512 + l] + g_part[(b * 4 + 3) * 512 + l];
    y = gelu_exact(y);

    __shared__ float red[16];
    __shared__ float mu_s, rstd_s;

    float s = y;
#pragma unroll
    for (int off = 16; off; off >>= 1) s += __shfl_down_sync(0xffffffffu, s, off);
    if ((l & 31) == 0) red[l >> 5] = s;
    __syncthreads();
    if (l == 0) {
        float S = 0.f;
        for (int i = 0; i < 16; i++) S += red[i];
        mu_s = S * (1.0f / 512.0f);
    }
    __syncthreads();
    float mu = mu_s;

    float dv = y - mu;
    float q = dv * dv;
#pragma unroll
    for (int off = 16; off; off >>= 1) q += __shfl_down_sync(0xffffffffu, q, off);
    if ((l & 31) == 0) red[l >> 5] = q;
    __syncthreads();
    if (l == 0) {
        float Q = 0.f;
        for (int i = 0; i < 16; i++) Q += red[i];
        rstd_s = rsqrtf(Q * (1.0f / 512.0f) + 1e-5f);
    }
    __syncthreads();

    float attn = (y - mu) * rstd_s * lng[l] + lnb[l];
    g_scale[b * 512 + l] = 1.0f + attn;
}

// ---------------- K5: out = x * (1 + attn[b,c]) ----------------
// 2 bc per block, 8 front-batched float4 loads per thread (MLP_p1=8).
// Reversed block order exploits L2-resident tail of x left by pool.
// __ldcs: x is dead after this kernel, don't let its stream evict useful lines.
__global__ __launch_bounds__(256) void apply_kernel(const float* __restrict__ x,
                                                    float* __restrict__ out) {
    int pair = (NB * NC / 2 - 1) - blockIdx.x;
    int bc0 = pair * 2;
    const float4* xp = (const float4*)x + (size_t)bc0 * (HW / 4);
    float4* op = (float4*)out + (size_t)bc0 * (HW / 4);
    int t = threadIdx.x;

    float4 a0 = __ldcs(xp + t);
    float4 a1 = __ldcs(xp + t + 256);
    float4 a2 = __ldcs(xp + t + 512);
    float4 a3 = __ldcs(xp + t + 768);
    float4 b0 = __ldcs(xp + t + 1024);
    float4 b1 = __ldcs(xp + t + 1280);
    float4 b2 = __ldcs(xp + t + 1536);
    float4 b3 = __ldcs(xp + t + 1792);

    float s0 = g_scale[bc0];
    float s1 = g_scale[bc0 + 1];

    a0.x *= s0; a0.y *= s0; a0.z *= s0; a0.w *= s0;
    a1.x *= s0; a1.y *= s0; a1.z *= s0; a1.w *= s0;
    a2.x *= s0; a2.y *= s0; a2.z *= s0; a2.w *= s0;
    a3.x *= s0; a3.y *= s0; a3.z *= s0; a3.w *= s0;
    b0.x *= s1; b0.y *= s1; b0.z *= s1; b0.w *= s1;
    b1.x *= s1; b1.y *= s1; b1.z *= s1; b1.w *= s1;
    b2.x *= s1; b2.y *= s1; b2.z *= s1; b2.w *= s1;
    b3.x *= s1; b3.y *= s1; b3.z *= s1; b3.w *= s1;

    __stcs(op + t,        a0);
    __stcs(op + t + 256,  a1);
    __stcs(op + t + 512,  a2);
    __stcs(op + t + 768,  a3);
    __stcs(op + t + 1024, b0);
    __stcs(op + t + 1280, b1);
    __stcs(op + t + 1536, b2);
    __stcs(op + t + 1792, b3);
}

// ---------------- launch ----------------
extern "C" void kernel_launch(void* const* d_in, const int* in_sizes, int n_in,
                              void* d_out, int out_size) {
    const float* x    = (const float*)d_in[0];
    const float* xcw  = (const float*)d_in[1];
    const float* dtw  = (const float*)d_in[2];
    const float* dtb  = (const float*)d_in[3];
    const float* Ac   = (const float*)d_in[4];
    const float* Dcs  = (const float*)d_in[5];
    const float* wcin = (const float*)d_in[6];
    const float* bng  = (const float*)d_in[7];
    const float* bnb  = (const float*)d_in[8];
    const float* bnm  = (const float*)d_in[9];
    const float* bnv  = (const float*)d_in[10];
    const float* wco  = (const float*)d_in[11];
    const float* lng  = (const float*)d_in[12];
    const float* lnb  = (const float*)d_in[13];
    float* out = (float*)d_out;

    pool_kernel<<<NB * NC, 256>>>(x);
    proj_kernel<<<(NB * 2 * LL) / 256, 256>>>(xcw, dtw, dtb, wcin, bng, bnb, bnm, bnv);

    int smem_bytes = 4 * 512 * SSTR * (int)sizeof(float);   // 139,264 B
    cudaFuncSetAttribute(scan_kernel, cudaFuncAttributeMaxDynamicSharedMemorySize, smem_bytes);
    scan_kernel<<<NB * 2 * 2, 256, smem_bytes>>>(Ac, Dcs, wco);

    ln_kernel<<<NB, 512>>>(lng, lnb);

    apply_kernel<<<NB * NC / 2, 256>>>(x, out);
}

// round 4
// speedup vs baseline: 1.0434x; 1.0434x over previous
#include <cuda_runtime.h>
#include <math.h>

#define NB 32
#define NC 512
#define HW 4096
#define DC 32
#define NS 16
#define RK 32
#define LL 512
#define SSTR 17   // smem row stride (gcd(17,32)=1 -> conflict-free)

// ---------------- scratch (device globals; no allocation) ----------------
__device__ float g_avg[NB * NC];
__device__ float g_max[NB * NC];
__device__ float g_part[NB * 2 * 2 * LL];        // partial y sums per (b,k,half)[l_out]
__device__ float g_scale[NB * NC];               // 1 + attn

__device__ __forceinline__ float gelu_exact(float v) {
    return 0.5f * v * (1.0f + erff(v * 0.70710678118654752f));
}

// ---------------- K1: avg/max pool over HW per (b,c) ----------------
__global__ __launch_bounds__(256) void pool_kernel(const float* __restrict__ x) {
    int bc = blockIdx.x;
    const float4* xp = (const float4*)(x + (size_t)bc * HW);
    int t = threadIdx.x;

    float4 v0 = __ldg(xp + t);
    float4 v1 = __ldg(xp + t + 256);
    float4 v2 = __ldg(xp + t + 512);
    float4 v3 = __ldg(xp + t + 768);

    float s = ((v0.x + v0.y) + (v0.z + v0.w)) + ((v1.x + v1.y) + (v1.z + v1.w))
            + ((v2.x + v2.y) + (v2.z + v2.w)) + ((v3.x + v3.y) + (v3.z + v3.w));
    float m = fmaxf(fmaxf(fmaxf(v0.x, v0.y), fmaxf(v0.z, v0.w)),
                    fmaxf(fmaxf(v1.x, v1.y), fmaxf(v1.z, v1.w)));
    m = fmaxf(m, fmaxf(fmaxf(fmaxf(v2.x, v2.y), fmaxf(v2.z, v2.w)),
                       fmaxf(fmaxf(v3.x, v3.y), fmaxf(v3.z, v3.w))));

#pragma unroll
    for (int off = 16; off; off >>= 1) {
        s += __shfl_down_sync(0xffffffffu, s, off);
        m = fmaxf(m, __shfl_down_sync(0xffffffffu, m, off));
    }
    __shared__ float ss[8], sm[8];
    int w = t >> 5;
    if ((t & 31) == 0) { ss[w] = s; sm[w] = m; }
    __syncthreads();
    if (t < 8) {
        s = ss[t]; m = sm[t];
#pragma unroll
        for (int off = 4; off; off >>= 1) {
            s += __shfl_down_sync(0xffu, s, off);
            m = fmaxf(m, __shfl_down_sync(0xffu, m, off));
        }
        if (t == 0) {
            g_avg[bc] = s * (1.0f / (float)HW);
            g_max[bc] = m;
        }
    }
}

// ---------------- K2: FUSED proj + selective scan ----------------
// block = (b, k, d-half). Phase A computes delta/B/C/u for this block's 16 d's
// directly into smem (proj work duplicated across the two halves — cheap).
// Phase B runs the scan with lanes = 16 states, unroll 8.
__global__ __launch_bounds__(256) void fused_scan_kernel(
    const float* __restrict__ xcw,      // (2,64,32)
    const float* __restrict__ dtw,      // (2,32,32)
    const float* __restrict__ dtb,      // (2*32)
    const float* __restrict__ wcin,     // (32,2)
    const float* __restrict__ bng, const float* __restrict__ bnb,
    const float* __restrict__ bnm, const float* __restrict__ bnv,
    const float* __restrict__ Ac_logs,  // (64,16)
    const float* __restrict__ Dcs,      // (64)
    const float* __restrict__ wcout)    // (32)
{
    extern __shared__ float smem[];
    float* dsm = smem;                 // delta  [l][dd]  512*SSTR
    float* usm = dsm + 512 * SSTR;     // u      [l][dd]
    float* bsm = usm + 512 * SSTR;     // B      [l][n]
    float* csm = bsm + 512 * SSTR;     // C      [l][n]

    __shared__ float sW[64 * 32];      // xc_proj for this k
    __shared__ float sDt[16 * 32];     // dt_proj rows d0..d0+15
    __shared__ float sc[64], sg[32], sb[32], smn[32], svr[32], sbias[16], swo[16];

    int blk = blockIdx.x;
    int b = blk >> 2;
    int k = (blk >> 1) & 1;
    int half = blk & 1;
    int d0 = half * 16;

    int t = threadIdx.x;
    for (int i = t; i < 64 * 32; i += 256) sW[i] = xcw[k * 2048 + i];
    for (int i = t; i < 16 * 32; i += 256) sDt[i] = dtw[k * 1024 + (d0 + (i >> 5)) * 32 + (i & 31)];
    if (t < 64) sc[t] = wcin[t];
    if (t < 32) { sg[t] = bng[t]; sb[t] = bnb[t]; smn[t] = bnm[t]; svr[t] = bnv[t]; }
    if (t < 16) { sbias[t] = dtb[k * 32 + d0 + t]; swo[t] = wcout[d0 + t]; }
    __syncthreads();

    // ---- Phase A: per-l projections (each thread does 2 l's) ----
#pragma unroll
    for (int rep = 0; rep < 2; rep++) {
        int l = t + rep * 256;
        int ll = k ? (511 - l) : l;
        float av = g_avg[b * 512 + ll];
        float mx = g_max[b * 512 + ll];

        float h[32];
#pragma unroll
        for (int d = 0; d < 32; d++) {
            float pre = av * sc[d * 2] + mx * sc[d * 2 + 1];
            pre = (pre - smn[d]) * rsqrtf(svr[d] + 1e-5f);
            pre = pre * sg[d] + sb[d];
            h[d] = gelu_exact(pre);
        }
#pragma unroll
        for (int dd = 0; dd < 16; dd++) usm[l * SSTR + dd] = h[d0 + dd];

        float r[32];
#pragma unroll 4
        for (int c = 0; c < 32; c++) {
            float acc = 0.f;
#pragma unroll
            for (int d = 0; d < 32; d++) acc = fmaf(h[d], sW[c * 32 + d], acc);
            r[c] = acc;
        }
#pragma unroll 4
        for (int j = 0; j < 16; j++) {
            float accB = 0.f, accC = 0.f;
#pragma unroll
            for (int d = 0; d < 32; d++) {
                accB = fmaf(h[d], sW[(32 + j) * 32 + d], accB);
                accC = fmaf(h[d], sW[(48 + j) * 32 + d], accC);
            }
            bsm[l * SSTR + j] = accB;
            csm[l * SSTR + j] = accC;
        }
#pragma unroll 4
        for (int dd = 0; dd < 16; dd++) {
            float acc = sbias[dd];
#pragma unroll
            for (int rr = 0; rr < 32; rr++) acc = fmaf(r[rr], sDt[dd * 32 + rr], acc);
            dsm[l * SSTR + dd] = (acc > 20.f) ? acc : log1pf(__expf(acc));
        }
    }
    __syncthreads();

    // ---- Phase B: scan. lanes 0-15 / 16-31 are two state groups ----
    int warp = t >> 5, lane = t & 31;
    int sub = lane >> 4;        // half-warp id
    int n = lane & 15;          // state index
    int dd = warp * 2 + sub;    // local d (0..15)
    int kd = k * 32 + d0 + dd;

    float a  = -expf(Ac_logs[kd * 16 + n]);
    float Dv = Dcs[kd];
    float h = 0.f;

#pragma unroll 8
    for (int l = 0; l < 512; l++) {
        float delta = dsm[l * SSTR + dd];
        float u     = usm[l * SSTR + dd];
        float Bn    = bsm[l * SSTR + n];
        float Cn    = csm[l * SSTR + n];
        float dA = __expf(delta * a);
        h = fmaf(dA, h, delta * Bn * u);
        float c = h * Cn;
        c += __shfl_down_sync(0xffffffffu, c, 8, 16);
        c += __shfl_down_sync(0xffffffffu, c, 4, 16);
        c += __shfl_down_sync(0xffffffffu, c, 2, 16);
        c += __shfl_down_sync(0xffffffffu, c, 1, 16);
        if (n == 0) dsm[l * SSTR + dd] = fmaf(Dv, u, c);   // y over own delta slot
    }
    __syncthreads();

    // ---- weighted d-reduce, write (flipped for k=1) ----
    int base = b * 2 + k;
    for (int l = t; l < 512; l += 256) {
        float acc = 0.f;
#pragma unroll
        for (int dd2 = 0; dd2 < 16; dd2++)
            acc = fmaf(dsm[l * SSTR + dd2], swo[dd2], acc);
        int lo = k ? (511 - l) : l;
        g_part[(base * 2 + half) * 512 + lo] = acc;
    }
}

// ---------------- K3: gelu + LayerNorm over L -> 1+attn ----------------
__global__ __launch_bounds__(512) void ln_kernel(
    const float* __restrict__ lng, const float* __restrict__ lnb)
{
    int b = blockIdx.x;
    int l = threadIdx.x;   // 512 threads
    float y = g_part[(b * 4 + 0) * 512 + l] + g_part[(b * 4 + 1) * 512 + l]
            + g_part[(b * 4 + 2) * 512 + l] + g_part[(b * 4 + 3) * 512 + l];
    y = gelu_exact(y);

    __shared__ float red[16];
    __shared__ float mu_s, rstd_s;

    float s = y;
#pragma unroll
    for (int off = 16; off; off >>= 1) s += __shfl_down_sync(0xffffffffu, s, off);
    if ((l & 31) == 0) red[l >> 5] = s;
    __syncthreads();
    if (l == 0) {
        float S = 0.f;
        for (int i = 0; i < 16; i++) S += red[i];
        mu_s = S * (1.0f / 512.0f);
    }
    __syncthreads();
    float mu = mu_s;

    float dv = y - mu;
    float q = dv * dv;
#pragma unroll
    for (int off = 16; off; off >>= 1) q += __shfl_down_sync(0xffffffffu, q, off);
    if ((l & 31) == 0) red[l >> 5] = q;
    __syncthreads();
    if (l == 0) {
        float Q = 0.f;
        for (int i = 0; i < 16; i++) Q += red[i];
        rstd_s = rsqrtf(Q * (1.0f / 512.0f) + 1e-5f);
    }
    __syncthreads();

    float attn = (y - mu) * rstd_s * lng[l] + lnb[l];
    g_scale[b * 512 + l] = 1.0f + attn;
}

// ---------------- K4: out = x * (1 + attn[b,c]) ---- (R2 exact config) ----
__global__ __launch_bounds__(256) void apply_kernel(const float* __restrict__ x,
                                                    float* __restrict__ out) {
    int bc = (NB * NC - 1) - blockIdx.x;
    float s = g_scale[bc];
    const float4* xp = (const float4*)(x + (size_t)bc * HW);
    float4* op = (float4*)(out + (size_t)bc * HW);
    int t = threadIdx.x;

    float4 v0 = __ldg(xp + t);
    float4 v1 = __ldg(xp + t + 256);
    float4 v2 = __ldg(xp + t + 512);
    float4 v3 = __ldg(xp + t + 768);

    v0.x *= s; v0.y *= s; v0.z *= s; v0.w *= s;
    v1.x *= s; v1.y *= s; v1.z *= s; v1.w *= s;
    v2.x *= s; v2.y *= s; v2.z *= s; v2.w *= s;
    v3.x *= s; v3.y *= s; v3.z *= s; v3.w *= s;

    __stcs(op + t,       v0);
    __stcs(op + t + 256, v1);
    __stcs(op + t + 512, v2);
    __stcs(op + t + 768, v3);
}

// ---------------- launch ----------------
extern "C" void kernel_launch(void* const* d_in, const int* in_sizes, int n_in,
                              void* d_out, int out_size) {
    const float* x    = (const float*)d_in[0];
    const float* xcw  = (const float*)d_in[1];
    const float* dtw  = (const float*)d_in[2];
    const float* dtb  = (const float*)d_in[3];
    const float* Ac   = (const float*)d_in[4];
    const float* Dcs  = (const float*)d_in[5];
    const float* wcin = (const float*)d_in[6];
    const float* bng  = (const float*)d_in[7];
    const float* bnb  = (const float*)d_in[8];
    const float* bnm  = (const float*)d_in[9];
    const float* bnv  = (const float*)d_in[10];
    const float* wco  = (const float*)d_in[11];
    const float* lng  = (const float*)d_in[12];
    const float* lnb  = (const float*)d_in[13];
    float* out = (float*)d_out;

    pool_kernel<<<NB * NC, 256>>>(x);

    int smem_bytes = 4 * 512 * SSTR * (int)sizeof(float);   // 139,264 B dynamic
    cudaFuncSetAttribute(fused_scan_kernel, cudaFuncAttributeMaxDynamicSharedMemorySize, smem_bytes);
    fused_scan_kernel<<<NB * 2 * 2, 256, smem_bytes>>>(
        xcw, dtw, dtb, wcin, bng, bnb, bnm, bnv, Ac, Dcs, wco);

    ln_kernel<<<NB, 512>>>(lng, lnb);

    apply_kernel<<<NB * NC, 256>>>(x, out);
}

// round 5
// speedup vs baseline: 1.2288x; 1.1777x over previous
#include <cuda_runtime.h>
#include <math.h>

#define NB 32
#define NC 512
#define HW 4096
#define DC 32
#define NS 16
#define RK 32
#define LL 512
#define SSTR 17   // smem row stride (gcd(17,32)=1 -> conflict-free)

// ---------------- scratch (device globals; no allocation) ----------------
__device__ float g_avg[NB * NC];
__device__ float g_max[NB * NC];
__device__ float g_part[NB * 2 * 2 * LL];        // partial y sums per (b,k,half)[l_out]
__device__ float g_scale[NB * NC];               // 1 + attn

__device__ __forceinline__ float gelu_exact(float v) {
    return 0.5f * v * (1.0f + erff(v * 0.70710678118654752f));
}

// ---------------- K1: avg/max pool over HW per (b,c) ----------------
__global__ __launch_bounds__(256) void pool_kernel(const float* __restrict__ x) {
    int bc = blockIdx.x;
    const float4* xp = (const float4*)(x + (size_t)bc * HW);
    int t = threadIdx.x;

    float4 v0 = __ldg(xp + t);
    float4 v1 = __ldg(xp + t + 256);
    float4 v2 = __ldg(xp + t + 512);
    float4 v3 = __ldg(xp + t + 768);

    float s = ((v0.x + v0.y) + (v0.z + v0.w)) + ((v1.x + v1.y) + (v1.z + v1.w))
            + ((v2.x + v2.y) + (v2.z + v2.w)) + ((v3.x + v3.y) + (v3.z + v3.w));
    float m = fmaxf(fmaxf(fmaxf(v0.x, v0.y), fmaxf(v0.z, v0.w)),
                    fmaxf(fmaxf(v1.x, v1.y), fmaxf(v1.z, v1.w)));
    m = fmaxf(m, fmaxf(fmaxf(fmaxf(v2.x, v2.y), fmaxf(v2.z, v2.w)),
                       fmaxf(fmaxf(v3.x, v3.y), fmaxf(v3.z, v3.w))));

#pragma unroll
    for (int off = 16; off; off >>= 1) {
        s += __shfl_down_sync(0xffffffffu, s, off);
        m = fmaxf(m, __shfl_down_sync(0xffffffffu, m, off));
    }
    __shared__ float ss[8], sm[8];
    int w = t >> 5;
    if ((t & 31) == 0) { ss[w] = s; sm[w] = m; }
    __syncthreads();
    if (t < 8) {
        s = ss[t]; m = sm[t];
#pragma unroll
        for (int off = 4; off; off >>= 1) {
            s += __shfl_down_sync(0xffu, s, off);
            m = fmaxf(m, __shfl_down_sync(0xffu, m, off));
        }
        if (t == 0) {
            g_avg[bc] = s * (1.0f / (float)HW);
            g_max[bc] = m;
        }
    }
}

// ---------------- K2: FUSED proj + selective scan ----------------
__global__ __launch_bounds__(256) void fused_scan_kernel(
    const float* __restrict__ xcw,      // (2,64,32)
    const float* __restrict__ dtw,      // (2,32,32)
    const float* __restrict__ dtb,      // (2*32)
    const float* __restrict__ wcin,     // (32,2)
    const float* __restrict__ bng, const float* __restrict__ bnb,
    const float* __restrict__ bnm, const float* __restrict__ bnv,
    const float* __restrict__ Ac_logs,  // (64,16)
    const float* __restrict__ Dcs,      // (64)
    const float* __restrict__ wcout)    // (32)
{
    extern __shared__ float smem[];
    float* dsm = smem;                 // delta  [l][dd]  512*SSTR
    float* usm = dsm + 512 * SSTR;     // u      [l][dd]
    float* bsm = usm + 512 * SSTR;     // B      [l][n]
    float* csm = bsm + 512 * SSTR;     // C      [l][n]
    float* ysm = csm + 512 * SSTR;     // y      [l][dd]  (separate: no in-loop aliasing churn)

    __shared__ float sW[64 * 32];      // xc_proj for this k
    __shared__ float sDt[16 * 32];     // dt_proj rows d0..d0+15
    __shared__ float sc[64], sg[32], sb[32], smn[32], svr[32], sbias[16], swo[16];

    int blk = blockIdx.x;
    int b = blk >> 2;
    int k = (blk >> 1) & 1;
    int half = blk & 1;
    int d0 = half * 16;

    int t = threadIdx.x;
    for (int i = t; i < 64 * 32; i += 256) sW[i] = xcw[k * 2048 + i];
    for (int i = t; i < 16 * 32; i += 256) sDt[i] = dtw[k * 1024 + (d0 + (i >> 5)) * 32 + (i & 31)];
    if (t < 64) sc[t] = wcin[t];
    if (t < 32) { sg[t] = bng[t]; sb[t] = bnb[t]; smn[t] = bnm[t]; svr[t] = bnv[t]; }
    if (t < 16) { sbias[t] = dtb[k * 32 + d0 + t]; swo[t] = wcout[d0 + t]; }
    __syncthreads();

    // ---- Phase A: per-l projections (each thread does 2 l's) ----
#pragma unroll
    for (int rep = 0; rep < 2; rep++) {
        int l = t + rep * 256;
        int ll = k ? (511 - l) : l;
        float av = g_avg[b * 512 + ll];
        float mx = g_max[b * 512 + ll];

        float h[32];
#pragma unroll
        for (int d = 0; d < 32; d++) {
            float pre = av * sc[d * 2] + mx * sc[d * 2 + 1];
            pre = (pre - smn[d]) * rsqrtf(svr[d] + 1e-5f);
            pre = pre * sg[d] + sb[d];
            h[d] = gelu_exact(pre);
        }
#pragma unroll
        for (int dd = 0; dd < 16; dd++) usm[l * SSTR + dd] = h[d0 + dd];

        float r[32];
#pragma unroll 4
        for (int c = 0; c < 32; c++) {
            float acc = 0.f;
#pragma unroll
            for (int d = 0; d < 32; d++) acc = fmaf(h[d], sW[c * 32 + d], acc);
            r[c] = acc;
        }
#pragma unroll 4
        for (int j = 0; j < 16; j++) {
            float accB = 0.f, accC = 0.f;
#pragma unroll
            for (int d = 0; d < 32; d++) {
                accB = fmaf(h[d], sW[(32 + j) * 32 + d], accB);
                accC = fmaf(h[d], sW[(48 + j) * 32 + d], accC);
            }
            bsm[l * SSTR + j] = accB;
            csm[l * SSTR + j] = accC;
        }
#pragma unroll 4
        for (int dd = 0; dd < 16; dd++) {
            float acc = sbias[dd];
#pragma unroll
            for (int rr = 0; rr < 32; rr++) acc = fmaf(r[rr], sDt[dd * 32 + rr], acc);
            dsm[l * SSTR + dd] = (acc > 20.f) ? acc : log1pf(__expf(acc));
        }
    }
    __syncthreads();

    // ---- Phase B: scan, burst-8 to break smem alias serialization ----
    int warp = t >> 5, lane = t & 31;
    int sub = lane >> 4;        // half-warp id
    int n = lane & 15;          // state index
    int dd = warp * 2 + sub;    // local d (0..15)
    int kd = k * 32 + d0 + dd;

    float a  = -expf(Ac_logs[kd * 16 + n]);
    float Dv = Dcs[kd];
    float h = 0.f;

#pragma unroll 1
    for (int l0 = 0; l0 < 512; l0 += 8) {
        float del[8], uu[8], Bn8[8], Cn8[8];
#pragma unroll
        for (int j = 0; j < 8; j++) {
            int l = l0 + j;
            del[j] = dsm[l * SSTR + dd];
            uu[j]  = usm[l * SSTR + dd];
            Bn8[j] = bsm[l * SSTR + n];
            Cn8[j] = csm[l * SSTR + n];
        }
        float yb[8];
#pragma unroll
        for (int j = 0; j < 8; j++) {
            float dA = __expf(del[j] * a);
            h = fmaf(dA, h, del[j] * Bn8[j] * uu[j]);
            float c = h * Cn8[j];
            c += __shfl_down_sync(0xffffffffu, c, 8, 16);
            c += __shfl_down_sync(0xffffffffu, c, 4, 16);
            c += __shfl_down_sync(0xffffffffu, c, 2, 16);
            c += __shfl_down_sync(0xffffffffu, c, 1, 16);
            yb[j] = fmaf(Dv, uu[j], c);
        }
        if (n == 0) {
#pragma unroll
            for (int j = 0; j < 8; j++) ysm[(l0 + j) * SSTR + dd] = yb[j];
        }
    }
    __syncthreads();

    // ---- weighted d-reduce, write (flipped for k=1) ----
    int base = b * 2 + k;
    for (int l = t; l < 512; l += 256) {
        float acc = 0.f;
#pragma unroll
        for (int dd2 = 0; dd2 < 16; dd2++)
            acc = fmaf(ysm[l * SSTR + dd2], swo[dd2], acc);
        int lo = k ? (511 - l) : l;
        g_part[(base * 2 + half) * 512 + lo] = acc;
    }
}

// ---------------- K3: gelu + LayerNorm over L -> 1+attn ----------------
__global__ __launch_bounds__(512) void ln_kernel(
    const float* __restrict__ lng, const float* __restrict__ lnb)
{
    int b = blockIdx.x;
    int l = threadIdx.x;   // 512 threads
    float y = g_part[(b * 4 + 0) * 512 + l] + g_part[(b * 4 + 1) * 512 + l]
            + g_part[(b * 4 + 2) * 512 + l] + g_part[(b * 4 + 3) * 512 + l];
    y = gelu_exact(y);

    __shared__ float red[16];
    __shared__ float mu_s, rstd_s;

    float s = y;
#pragma unroll
    for (int off = 16; off; off >>= 1) s += __shfl_down_sync(0xffffffffu, s, off);
    if ((l & 31) == 0) red[l >> 5] = s;
    __syncthreads();
    if (l == 0) {
        float S = 0.f;
        for (int i = 0; i < 16; i++) S += red[i];
        mu_s = S * (1.0f / 512.0f);
    }
    __syncthreads();
    float mu = mu_s;

    float dv = y - mu;
    float q = dv * dv;
#pragma unroll
    for (int off = 16; off; off >>= 1) q += __shfl_down_sync(0xffffffffu, q, off);
    if ((l & 31) == 0) red[l >> 5] = q;
    __syncthreads();
    if (l == 0) {
        float Q = 0.f;
        for (int i = 0; i < 16; i++) Q += red[i];
        rstd_s = rsqrtf(Q * (1.0f / 512.0f) + 1e-5f);
    }
    __syncthreads();

    float attn = (y - mu) * rstd_s * lng[l] + lnb[l];
    g_scale[b * 512 + l] = 1.0f + attn;
}

// ---------------- K4: out = x * (1 + attn[b,c]) ---- (R2/R4 best config) ----
__global__ __launch_bounds__(256) void apply_kernel(const float* __restrict__ x,
                                                    float* __restrict__ out) {
    int bc = (NB * NC - 1) - blockIdx.x;
    float s = g_scale[bc];
    const float4* xp = (const float4*)(x + (size_t)bc * HW);
    float4* op = (float4*)(out + (size_t)bc * HW);
    int t = threadIdx.x;

    float4 v0 = __ldg(xp + t);
    float4 v1 = __ldg(xp + t + 256);
    float4 v2 = __ldg(xp + t + 512);
    float4 v3 = __ldg(xp + t + 768);

    v0.x *= s; v0.y *= s; v0.z *= s; v0.w *= s;
    v1.x *= s; v1.y *= s; v1.z *= s; v1.w *= s;
    v2.x *= s; v2.y *= s; v2.z *= s; v2.w *= s;
    v3.x *= s; v3.y *= s; v3.z *= s; v3.w *= s;

    __stcs(op + t,       v0);
    __stcs(op + t + 256, v1);
    __stcs(op + t + 512, v2);
    __stcs(op + t + 768, v3);
}

// ---------------- launch ----------------
extern "C" void kernel_launch(void* const* d_in, const int* in_sizes, int n_in,
                              void* d_out, int out_size) {
    const float* x    = (const float*)d_in[0];
    const float* xcw  = (const float*)d_in[1];
    const float* dtw  = (const float*)d_in[2];
    const float* dtb  = (const float*)d_in[3];
    const float* Ac   = (const float*)d_in[4];
    const float* Dcs  = (const float*)d_in[5];
    const float* wcin = (const float*)d_in[6];
    const float* bng  = (const float*)d_in[7];
    const float* bnb  = (const float*)d_in[8];
    const float* bnm  = (const float*)d_in[9];
    const float* bnv  = (const float*)d_in[10];
    const float* wco  = (const float*)d_in[11];
    const float* lng  = (const float*)d_in[12];
    const float* lnb  = (const float*)d_in[13];
    float* out = (float*)d_out;

    pool_kernel<<<NB * NC, 256>>>(x);

    int smem_bytes = 5 * 512 * SSTR * (int)sizeof(float);   // 174,080 B dynamic
    cudaFuncSetAttribute(fused_scan_kernel, cudaFuncAttributeMaxDynamicSharedMemorySize, smem_bytes);
    fused_scan_kernel<<<NB * 2 * 2, 256, smem_bytes>>>(
        xcw, dtw, dtb, wcin, bng, bnb, bnm, bnv, Ac, Dcs, wco);

    ln_kernel<<<NB, 512>>>(lng, lnb);

    apply_kernel<<<NB * NC, 256>>>(x, out);
}